// round 10
// baseline (speedup 1.0000x reference)
#include <cuda_runtime.h>

#define T_TOTAL    262144
#define NF         64
#define XR4        (NF / 4)            // 16 float4 per x row
#define OR4        (4 * NF / 4)        // 64 float4 per out row
#define TILE_ROWS  256
#define HALO       90
#define SROWS      (TILE_ROWS + HALO)  // 346
#define SMEM_F4    (SROWS * XR4)       // 5536 float4
#define SMEM_BYTES (SMEM_F4 * 16)      // 88576 B
#define THREADS    256
#define GROUP_ROWS 16                  // 16 groups of 16 rows

__device__ __forceinline__ float4 f4add(float4 a, float4 b) {
    return make_float4(a.x + b.x, a.y + b.y, a.z + b.z, a.w + b.w);
}
__device__ __forceinline__ float4 f4sub(float4 a, float4 b) {
    return make_float4(a.x - b.x, a.y - b.y, a.z - b.z, a.w - b.w);
}
__device__ __forceinline__ float4 f4scale(float4 a, float s) {
    return make_float4(a.x * s, a.y * s, a.z * s, a.w * s);
}

__global__ void __launch_bounds__(THREADS, 2)
ma_kernel(const float* __restrict__ x, float* __restrict__ out) {
    extern __shared__ float4 sm4[];                // [SROWS][XR4]

    const int t    = threadIdx.x;
    const int blk  = blockIdx.x;
    const int base = blk * TILE_ROWS - HALO;       // global row of smem row 0

    // ---- Phase 1: stream tile + halo into smem (float4, coalesced) ----
    const float4* x4 = (const float4*)x;           // row stride XR4
    #pragma unroll 6
    for (int idx = t; idx < SMEM_F4; idx += THREADS) {
        int gr = base + (idx >> 4);
        float4 v;
        if (gr >= 0) {
            v = __ldcg(&x4[idx + base * XR4]);
        } else {
            v = make_float4(0.f, 0.f, 0.f, 0.f);   // zero-pad rows < 0
        }
        sm4[idx] = v;
    }
    __syncthreads();

    // ---- Phase 2: 4 columns per thread, 16-row strip per group ----
    const int c   = t & (XR4 - 1);                 // column group 0..15
    const int g   = t >> 4;                        // row group 0..15
    const int lr0 = HALO + g * GROUP_ROWS;
    const int gr0 = blk * TILE_ROWS + g * GROUP_ROWS;

    float4 s7  = make_float4(0.f, 0.f, 0.f, 0.f);
    float4 s30 = s7, s90 = s7;

    // Entry sums over the 90 rows preceding the strip (zero-padded for blk 0).
    #pragma unroll 10
    for (int k = 1; k <= HALO; k++) {
        float4 v = sm4[(lr0 - k) * XR4 + c];
        s90 = f4add(s90, v);
        if (k <= 30) s30 = f4add(s30, v);
        if (k <= 7)  s7  = f4add(s7, v);
    }

    const float inv7  = 1.0f / 7.0f;
    const float inv30 = 1.0f / 30.0f;
    const float inv90 = 1.0f / 90.0f;

    float4* oc = (float4*)out + c;                 // row stride OR4

    if (gr0 < 90) {
        // Careful region (only blk 0, groups 0..5): expanding divisors;
        // zero-padded halo makes sliding sums equal the cumsum automatically.
        #pragma unroll
        for (int j = 0; j < GROUP_ROWS; j++) {
            int lr = lr0 + j;
            int gi = gr0 + j;
            float4 v   = sm4[lr * XR4 + c];
            float4 v7  = sm4[(lr - 7)  * XR4 + c];
            float4 v30 = sm4[(lr - 30) * XR4 + c];
            float4 v90 = sm4[(lr - 90) * XR4 + c];
            s7  = f4add(s7,  f4sub(v, v7));
            s30 = f4add(s30, f4sub(v, v30));
            s90 = f4add(s90, f4sub(v, v90));
            float rn  = 1.0f / (float)(gi + 1);
            float r7  = (gi >= 6)  ? inv7  : rn;
            float r30 = (gi >= 29) ? inv30 : rn;
            float r90 = (gi >= 89) ? inv90 : rn;
            float4* o = oc + gi * OR4;
            __stcs(o,           v);
            __stcs(o + XR4,     f4scale(s7,  r7));
            __stcs(o + 2 * XR4, f4scale(s30, r30));
            __stcs(o + 3 * XR4, f4scale(s90, r90));
        }
    } else {
        #pragma unroll
        for (int j = 0; j < GROUP_ROWS; j++) {
            int lr = lr0 + j;
            int gi = gr0 + j;
            float4 v   = sm4[lr * XR4 + c];
            float4 v7  = sm4[(lr - 7)  * XR4 + c];
            float4 v30 = sm4[(lr - 30) * XR4 + c];
            float4 v90 = sm4[(lr - 90) * XR4 + c];
            s7  = f4add(s7,  f4sub(v, v7));
            s30 = f4add(s30, f4sub(v, v30));
            s90 = f4add(s90, f4sub(v, v90));
            float4* o = oc + gi * OR4;
            __stcs(o,           v);
            __stcs(o + XR4,     f4scale(s7,  inv7));
            __stcs(o + 2 * XR4, f4scale(s30, inv30));
            __stcs(o + 3 * XR4, f4scale(s90, inv90));
        }
    }
}

extern "C" void kernel_launch(void* const* d_in, const int* in_sizes, int n_in,
                              void* d_out, int out_size) {
    const float* x  = (const float*)d_in[0];
    float*      out = (float*)d_out;
    static int attr_set = 0;
    if (!attr_set) {
        cudaFuncSetAttribute(ma_kernel,
                             cudaFuncAttributeMaxDynamicSharedMemorySize,
                             SMEM_BYTES);
        attr_set = 1;
    }
    int n_blocks = T_TOTAL / TILE_ROWS;            // 1024
    ma_kernel<<<n_blocks, THREADS, SMEM_BYTES>>>(x, out);
}